// round 9
// baseline (speedup 1.0000x reference)
#include <cuda_runtime.h>
#include <cuda_bf16.h>
#include <cstdint>
#include <cstddef>

#define D_MODEL 1024
#define N_HEADS 16
#define HEAD_DIM 64
#define BATCH 2
#define SEQ 2048
#define ROWS (BATCH * SEQ)   // 4096

// ---------------- scratch (__device__ globals; allocation-free rule) -------
__device__ __nv_bfloat16 g_xh[ROWS * D_MODEL];
__device__ __nv_bfloat16 g_xl[ROWS * D_MODEL];
__device__ __nv_bfloat16 g_qh[ROWS * D_MODEL];
__device__ __nv_bfloat16 g_ql[ROWS * D_MODEL];
__device__ __nv_bfloat16 g_kh[ROWS * D_MODEL];
__device__ __nv_bfloat16 g_kl[ROWS * D_MODEL];
__device__ __nv_bfloat16 g_vh[ROWS * D_MODEL];
__device__ __nv_bfloat16 g_vl[ROWS * D_MODEL];
__device__ __nv_bfloat16 g_ah[ROWS * D_MODEL];
__device__ __nv_bfloat16 g_al[ROWS * D_MODEL];
__device__ __nv_bfloat16 g_wh[4 * D_MODEL * D_MODEL];  // transposed [N,K]
__device__ __nv_bfloat16 g_wl[4 * D_MODEL * D_MODEL];

// ---------------- helpers --------------------------------------------------
__device__ __forceinline__ uint32_t smem_u32(const void* p) {
    uint32_t a;
    asm("{ .reg .u64 t; cvta.to.shared.u64 t, %1; cvt.u32.u64 %0, t; }"
        : "=r"(a) : "l"(p));
    return a;
}

__device__ __forceinline__ void cp16(uint32_t s, const void* g) {
    asm volatile("cp.async.cg.shared.global [%0], [%1], 16;" :: "r"(s), "l"(g));
}
#define CP_COMMIT() asm volatile("cp.async.commit_group;" ::: "memory")
#define CP_WAIT(n)  asm volatile("cp.async.wait_group %0;" :: "n"(n) : "memory")

__device__ __forceinline__ void ldsm_x4(uint32_t addr, uint32_t& r0, uint32_t& r1,
                                        uint32_t& r2, uint32_t& r3) {
    asm volatile("ldmatrix.sync.aligned.m8n8.x4.shared.b16 {%0,%1,%2,%3}, [%4];"
                 : "=r"(r0), "=r"(r1), "=r"(r2), "=r"(r3) : "r"(addr));
}

__device__ __forceinline__ void ldsm_x4_t(uint32_t addr, uint32_t& r0, uint32_t& r1,
                                          uint32_t& r2, uint32_t& r3) {
    asm volatile("ldmatrix.sync.aligned.m8n8.x4.trans.shared.b16 {%0,%1,%2,%3}, [%4];"
                 : "=r"(r0), "=r"(r1), "=r"(r2), "=r"(r3) : "r"(addr));
}

__device__ __forceinline__ void mma16816(float* c, const uint32_t* a, const uint32_t* b) {
    asm volatile(
        "mma.sync.aligned.m16n8k16.row.col.f32.bf16.bf16.f32 "
        "{%0,%1,%2,%3},{%4,%5,%6,%7},{%8,%9},{%0,%1,%2,%3};"
        : "+f"(c[0]), "+f"(c[1]), "+f"(c[2]), "+f"(c[3])
        : "r"(a[0]), "r"(a[1]), "r"(a[2]), "r"(a[3]), "r"(b[0]), "r"(b[1]));
}

__device__ __forceinline__ uint32_t pack_bf16(float lo, float hi) {
    uint32_t r;
    asm("cvt.rn.bf16x2.f32 %0, %1, %2;" : "=r"(r) : "f"(hi), "f"(lo));
    return r;
}

__device__ __forceinline__ float bf16_rt(float v) {
    return __bfloat162float(__float2bfloat16(v));
}

__device__ __forceinline__ float ex2(float x) {
    float r;
    asm("ex2.approx.f32 %0, %1;" : "=f"(r) : "f"(x));
    return r;
}

// ---------------------------------------------------------------------------
// Pipelined split-bf16 GEMM (cp.async double-buffer). Unchanged from R6.
// ---------------------------------------------------------------------------
#define GK 1024
#define NCH (GK / 32)                // 32
#define TS 40
#define TILE_HALVES (128 * TS)       // 5120
#define TILE_BYTES (TILE_HALVES * 2) // 10240
#define STAGE_BYTES (4 * TILE_BYTES) // 40960
#define GEMM_SMEM (2 * STAGE_BYTES)  // 81920

template <int QKV>
__global__ __launch_bounds__(256, 1) void gemm_pipe(
    const __nv_bfloat16* __restrict__ Ah, const __nv_bfloat16* __restrict__ Al,
    const __nv_bfloat16* __restrict__ Bh, const __nv_bfloat16* __restrict__ Bl,
    float* __restrict__ C, __nv_bfloat16* __restrict__ H,
    __nv_bfloat16* __restrict__ L) {
    extern __shared__ __align__(16) char gsm[];
    if (QKV) {
        const size_t zo = (size_t)blockIdx.z * D_MODEL * D_MODEL;
        Ah = g_xh; Al = g_xl;
        Bh = g_wh + zo; Bl = g_wl + zo;
        H = blockIdx.z == 0 ? g_qh : blockIdx.z == 1 ? g_kh : g_vh;
        L = blockIdx.z == 0 ? g_ql : blockIdx.z == 1 ? g_kl : g_vl;
    }

    const int tid = threadIdx.x;
    const int lane = tid & 31;
    const int wid = tid >> 5;
    const int wm = wid & 3;
    const int wn = wid >> 2;
    const int mBase = wm * 32;
    const int nBase = wn * 64;
    const int bm = blockIdx.y * 128;
    const int bn = blockIdx.x * 128;
    const uint32_t sb = smem_u32(gsm);

    const int ld_r = tid >> 2, ld_c = (tid & 3) * 8;

    float c[2][8][4];
#pragma unroll
    for (int mt = 0; mt < 2; mt++)
#pragma unroll
        for (int nt = 0; nt < 8; nt++)
#pragma unroll
            for (int j = 0; j < 4; j++) c[mt][nt][j] = 0.0f;

    const int a_row = lane & 15;
    const int a_koff = (lane >> 4) * 8;
    const int b_nrow = ((lane >> 4) * 8) + (lane & 7);
    const int b_koff = ((lane >> 3) & 1) * 8;

    auto issue = [&](int ch, int stage) {
        const int k0 = ch * 32;
        const __nv_bfloat16* srcs[4] = {
            Ah + (size_t)bm * GK + k0, Al + (size_t)bm * GK + k0,
            Bh + (size_t)bn * GK + k0, Bl + (size_t)bn * GK + k0};
        const uint32_t sbase = sb + stage * STAGE_BYTES;
#pragma unroll
        for (int t = 0; t < 4; t++) {
#pragma unroll
            for (int it = 0; it < 2; it++) {
                int r = ld_r + it * 64;
                cp16(sbase + t * TILE_BYTES + (r * TS + ld_c) * 2,
                     srcs[t] + (size_t)r * GK + ld_c);
            }
        }
        CP_COMMIT();
    };

    issue(0, 0);

    for (int ch = 0; ch < NCH; ch++) {
        if (ch + 1 < NCH) {
            issue(ch + 1, (ch + 1) & 1);
            CP_WAIT(1);
        } else {
            CP_WAIT(0);
        }
        __syncthreads();
        const uint32_t base = sb + (ch & 1) * STAGE_BYTES;

#pragma unroll
        for (int ks = 0; ks < 2; ks++) {
            uint32_t aH[2][4], aL[2][4], b[8][2];
#pragma unroll
            for (int mt = 0; mt < 2; mt++) {
                uint32_t off = ((mBase + mt * 16 + a_row) * TS + ks * 16 + a_koff) * 2;
                ldsm_x4(base + off, aH[mt][0], aH[mt][1], aH[mt][2], aH[mt][3]);
                ldsm_x4(base + TILE_BYTES + off, aL[mt][0], aL[mt][1], aL[mt][2], aL[mt][3]);
            }
#pragma unroll
            for (int g = 0; g < 4; g++) {
                uint32_t off = ((nBase + g * 16 + b_nrow) * TS + ks * 16 + b_koff) * 2;
                ldsm_x4(base + 2 * TILE_BYTES + off,
                        b[2 * g][0], b[2 * g][1], b[2 * g + 1][0], b[2 * g + 1][1]);
            }
#pragma unroll
            for (int mt = 0; mt < 2; mt++)
#pragma unroll
                for (int nt = 0; nt < 8; nt++) mma16816(c[mt][nt], aH[mt], b[nt]);
#pragma unroll
            for (int mt = 0; mt < 2; mt++)
#pragma unroll
                for (int nt = 0; nt < 8; nt++) mma16816(c[mt][nt], aL[mt], b[nt]);
#pragma unroll
            for (int g = 0; g < 4; g++) {
                uint32_t off = ((nBase + g * 16 + b_nrow) * TS + ks * 16 + b_koff) * 2;
                ldsm_x4(base + 3 * TILE_BYTES + off,
                        b[2 * g][0], b[2 * g][1], b[2 * g + 1][0], b[2 * g + 1][1]);
            }
#pragma unroll
            for (int mt = 0; mt < 2; mt++)
#pragma unroll
                for (int nt = 0; nt < 8; nt++) mma16816(c[mt][nt], aH[mt], b[nt]);
        }
        __syncthreads();
    }

#pragma unroll
    for (int mt = 0; mt < 2; mt++) {
#pragma unroll
        for (int half = 0; half < 2; half++) {
            int row = bm + mBase + mt * 16 + (lane >> 2) + half * 8;
#pragma unroll
            for (int nt = 0; nt < 8; nt++) {
                int col = bn + nBase + nt * 8 + (lane & 3) * 2;
                float v0 = c[mt][nt][2 * half];
                float v1 = c[mt][nt][2 * half + 1];
                if (QKV) {
                    size_t off = (size_t)row * D_MODEL + col;
                    float h0 = bf16_rt(v0), h1 = bf16_rt(v1);
                    *(uint32_t*)(H + off) = pack_bf16(h0, h1);
                    *(uint32_t*)(L + off) = pack_bf16(v0 - h0, v1 - h1);
                } else {
                    *(float2*)(C + (size_t)row * D_MODEL + col) = make_float2(v0, v1);
                }
            }
        }
    }
}

// ---------------------------------------------------------------------------
// Conversion kernels
// ---------------------------------------------------------------------------
__global__ __launch_bounds__(256) void split_fp32(const float* __restrict__ s,
                                                  __nv_bfloat16* __restrict__ h,
                                                  __nv_bfloat16* __restrict__ l) {
    int i = blockIdx.x * 256 + threadIdx.x;
    float4 v = ((const float4*)s)[i];
    float a[4] = {v.x, v.y, v.z, v.w};
    uint32_t hh[2], ll[2];
#pragma unroll
    for (int j = 0; j < 2; j++) {
        float h0 = bf16_rt(a[2 * j]), h1 = bf16_rt(a[2 * j + 1]);
        hh[j] = pack_bf16(h0, h1);
        ll[j] = pack_bf16(a[2 * j] - h0, a[2 * j + 1] - h1);
    }
    ((uint32_t*)h)[2 * i] = hh[0];
    ((uint32_t*)h)[2 * i + 1] = hh[1];
    ((uint32_t*)l)[2 * i] = ll[0];
    ((uint32_t*)l)[2 * i + 1] = ll[1];
}

__global__ __launch_bounds__(256) void transpose_split4(const float* __restrict__ w0,
                                                        const float* __restrict__ w1,
                                                        const float* __restrict__ w2,
                                                        const float* __restrict__ w3) {
    __shared__ float t[32][33];
    const int z = blockIdx.z;
    const float* W = z == 0 ? w0 : z == 1 ? w1 : z == 2 ? w2 : w3;
    __nv_bfloat16* Th = g_wh + (size_t)z * D_MODEL * D_MODEL;
    __nv_bfloat16* Tl = g_wl + (size_t)z * D_MODEL * D_MODEL;

    int x = blockIdx.x * 32 + threadIdx.x;
    int y0 = blockIdx.y * 32;
#pragma unroll
    for (int j = 0; j < 32; j += 8)
        t[threadIdx.y + j][threadIdx.x] = W[(size_t)(y0 + threadIdx.y + j) * D_MODEL + x];
    __syncthreads();
    int xo = blockIdx.y * 32 + threadIdx.x;
    int yo = blockIdx.x * 32;
#pragma unroll
    for (int j = 0; j < 32; j += 8) {
        float v = t[threadIdx.x][threadIdx.y + j];
        float hv = bf16_rt(v);
        Th[(size_t)(yo + threadIdx.y + j) * D_MODEL + xo] = __float2bfloat16(v);
        Tl[(size_t)(yo + threadIdx.y + j) * D_MODEL + xo] = __float2bfloat16(v - hv);
    }
}

// ---------------------------------------------------------------------------
// Tensor-core causal flash attention, split-bf16, cp.async KV prefetch.
// BLOCK_M=128, BLOCK_N=64. 256 threads (8 warps x 16 q-rows).
// Smem: Q(h,l) 2x18432 + 2 stages x KV(4x9216) = 110592 B -> 2 CTAs/SM
// (launch_bounds(256,2), regs <= 128) = 16 warps/SM.
// S = QhKh+QlKh+QhKl ; PV = PhVh+PlVh+PhVl. Softmax in base-2 domain.
// ---------------------------------------------------------------------------
#define TS2 72
#define ATILE_B (64 * TS2 * 2)       // 9216 B per 64-row tile
#define QTILE_B (128 * TS2 * 2)      // 18432 B per 128-row Q tile
#define KV_STAGE (4 * ATILE_B)       // 36864
#define ATTN_SMEM (2 * QTILE_B + 2 * KV_STAGE)  // 110592

__global__ __launch_bounds__(256, 2) void attn_tc() {
    extern __shared__ __align__(16) char asmc[];
    const uint32_t sb = smem_u32(asmc);

    const int tid = threadIdx.x;
    const int lane = tid & 31;
    const int wq = tid >> 5;                     // 0..7
    const int qb = gridDim.x - 1 - blockIdx.x;   // heavy blocks first
    const int bh = blockIdx.y;
    const int b = bh >> 4, h = bh & 15;

    // ---- Q loads (2 tiles x 128 rows x 64 halves) ----
    {
        const size_t base = (size_t)(b * SEQ + qb * 128) * D_MODEL + h * 64;
#pragma unroll
        for (int it = 0; it < 4; it++) {
            int idx = tid + it * 256;            // 0..1023
            int r = idx >> 3, c8 = (idx & 7) * 8;
            size_t g = base + (size_t)r * D_MODEL + c8;
            uint32_t so = (r * TS2 + c8) * 2;
            cp16(sb + so, g_qh + g);
            cp16(sb + QTILE_B + so, g_ql + g);
        }
        CP_COMMIT();
    }

    auto issue_kv = [&](int kb, int stage) {
        const size_t base = (size_t)(b * SEQ + kb * 64) * D_MODEL + h * 64;
        const uint32_t kvb = sb + 2 * QTILE_B + stage * KV_STAGE;
#pragma unroll
        for (int it = 0; it < 2; it++) {
            int idx = tid + it * 256;            // 0..511
            int r = idx >> 3, c8 = (idx & 7) * 8;
            size_t g = base + (size_t)r * D_MODEL + c8;
            uint32_t so = (r * TS2 + c8) * 2;
            cp16(kvb + so, g_kh + g);
            cp16(kvb + ATILE_B + so, g_kl + g);
            cp16(kvb + 2 * ATILE_B + so, g_vh + g);
            cp16(kvb + 3 * ATILE_B + so, g_vl + g);
        }
        CP_COMMIT();
    };

    issue_kv(0, 0);

    float O[8][4];
#pragma unroll
    for (int nt = 0; nt < 8; nt++)
#pragma unroll
        for (int j = 0; j < 4; j++) O[nt][j] = 0.0f;
    float mrow[2] = {-1e30f, -1e30f};
    float lrow[2] = {0.0f, 0.0f};

    // scale * log2(e): softmax entirely in base-2 domain
    const float scale2 = 0.03125f * 1.44269504088896f;

    const uint32_t a_off = ((wq * 16 + (lane & 15)) * TS2 + (lane >> 4) * 8) * 2;
    const uint32_t b_off = ((((lane >> 4) * 8) + (lane & 7)) * TS2 + ((lane >> 3) & 1) * 8) * 2;
    const uint32_t v_off = ((((lane >> 3) & 1) * 8 + (lane & 7)) * TS2 + (lane >> 4) * 8) * 2;

    const int row0 = qb * 128 + wq * 16 + (lane >> 2);
    const int nkb = 2 * qb + 2;                  // kb tiles to process

    for (int kb = 0; kb < nkb; kb++) {
        if (kb + 1 < nkb) {
            issue_kv(kb + 1, (kb + 1) & 1);
            CP_WAIT(1);
        } else {
            CP_WAIT(0);
        }
        __syncthreads();

        const uint32_t kvb = sb + 2 * QTILE_B + (kb & 1) * KV_STAGE;
        const uint32_t SKH = kvb, SKL = kvb + ATILE_B,
                       SVH = kvb + 2 * ATILE_B, SVL = kvb + 3 * ATILE_B;

        // ---- S = Q @ K^T (split) ----
        float s[8][4];
#pragma unroll
        for (int nt = 0; nt < 8; nt++)
#pragma unroll
            for (int j = 0; j < 4; j++) s[nt][j] = 0.0f;

#pragma unroll
        for (int ks = 0; ks < 4; ks++) {
            uint32_t aH[4], aL[4], bk[8][2];
            ldsm_x4(sb + a_off + ks * 32, aH[0], aH[1], aH[2], aH[3]);
            ldsm_x4(sb + QTILE_B + a_off + ks * 32, aL[0], aL[1], aL[2], aL[3]);
#pragma unroll
            for (int g = 0; g < 4; g++)
                ldsm_x4(SKH + b_off + g * 16 * TS2 * 2 + ks * 32,
                        bk[2 * g][0], bk[2 * g][1], bk[2 * g + 1][0], bk[2 * g + 1][1]);
#pragma unroll
            for (int nt = 0; nt < 8; nt++) mma16816(s[nt], aH, bk[nt]);
#pragma unroll
            for (int nt = 0; nt < 8; nt++) mma16816(s[nt], aL, bk[nt]);
#pragma unroll
            for (int g = 0; g < 4; g++)
                ldsm_x4(SKL + b_off + g * 16 * TS2 * 2 + ks * 32,
                        bk[2 * g][0], bk[2 * g][1], bk[2 * g + 1][0], bk[2 * g + 1][1]);
#pragma unroll
            for (int nt = 0; nt < 8; nt++) mma16816(s[nt], aH, bk[nt]);
        }

        // ---- scale + mask + online softmax (base-2) ----
        const bool need_mask = (kb * 64 + 63) > (qb * 128 + wq * 16);
#pragma unroll
        for (int i = 0; i < 2; i++) {
            const int rg = row0 + i * 8;
            float mx = -1e30f;
#pragma unroll
            for (int nt = 0; nt < 8; nt++) {
#pragma unroll
                for (int j = 0; j < 2; j++) {
                    float v = s[nt][2 * i + j] * scale2;
                    if (need_mask) {
                        int cg = kb * 64 + nt * 8 + (lane & 3) * 2 + j;
                        if (cg > rg) v = -1e30f;
                    }
                    s[nt][2 * i + j] = v;
                    mx = fmaxf(mx, v);
                }
            }
            mx = fmaxf(mx, __shfl_xor_sync(0xffffffffu, mx, 1));
            mx = fmaxf(mx, __shfl_xor_sync(0xffffffffu, mx, 2));
            float mn = fmaxf(mrow[i], mx);
            float alpha = ex2(mrow[i] - mn);
            mrow[i] = mn;
            float rs = 0.0f;
#pragma unroll
            for (int nt = 0; nt < 8; nt++) {
#pragma unroll
                for (int j = 0; j < 2; j++) {
                    float p = ex2(s[nt][2 * i + j] - mn);
                    s[nt][2 * i + j] = p;
                    rs += p;
                }
            }
            rs += __shfl_xor_sync(0xffffffffu, rs, 1);
            rs += __shfl_xor_sync(0xffffffffu, rs, 2);
            lrow[i] = lrow[i] * alpha + rs;
#pragma unroll
            for (int nt = 0; nt < 8; nt++) {
                O[nt][2 * i] *= alpha;
                O[nt][2 * i + 1] *= alpha;
            }
        }

        // ---- O += P @ V (split; P from registers) ----
#pragma unroll
        for (int g = 0; g < 4; g++) {
            uint32_t pH[4], pL[4];
#pragma unroll
            for (int q2 = 0; q2 < 2; q2++) {
#pragma unroll
                for (int half = 0; half < 2; half++) {
                    float v0 = s[2 * g + q2][2 * half];
                    float v1 = s[2 * g + q2][2 * half + 1];
                    float h0 = bf16_rt(v0), h1 = bf16_rt(v1);
                    pH[2 * q2 + half] = pack_bf16(h0, h1);
                    pL[2 * q2 + half] = pack_bf16(v0 - h0, v1 - h1);
                }
            }
            uint32_t bv[8][2];
#pragma unroll
            for (int gn = 0; gn < 4; gn++)
                ldsm_x4_t(SVH + v_off + (g * 16 * TS2 + gn * 16) * 2,
                          bv[2 * gn][0], bv[2 * gn][1], bv[2 * gn + 1][0], bv[2 * gn + 1][1]);
#pragma unroll
            for (int nt = 0; nt < 8; nt++) mma16816(O[nt], pH, bv[nt]);
#pragma unroll
            for (int nt = 0; nt < 8; nt++) mma16816(O[nt], pL, bv[nt]);
#pragma unroll
            for (int gn = 0; gn < 4; gn++)
                ldsm_x4_t(SVL + v_off + (g * 16 * TS2 + gn * 16) * 2,
                          bv[2 * gn][0], bv[2 * gn][1], bv[2 * gn + 1][0], bv[2 * gn + 1][1]);
#pragma unroll
            for (int nt = 0; nt < 8; nt++) mma16816(O[nt], pH, bv[nt]);
        }
        __syncthreads();
    }

    // ---- epilogue ----
#pragma unroll
    for (int i = 0; i < 2; i++) {
        float inv = 1.0f / lrow[i];
        size_t row = (size_t)(b * SEQ) + row0 + i * 8;
#pragma unroll
        for (int nt = 0; nt < 8; nt++) {
            size_t off = row * D_MODEL + h * 64 + nt * 8 + (lane & 3) * 2;
            float v0 = O[nt][2 * i] * inv;
            float v1 = O[nt][2 * i + 1] * inv;
            float h0 = bf16_rt(v0), h1 = bf16_rt(v1);
            *(uint32_t*)(g_ah + off) = pack_bf16(h0, h1);
            *(uint32_t*)(g_al + off) = pack_bf16(v0 - h0, v1 - h1);
        }
    }
}

// ---------------------------------------------------------------------------
// kernel_launch: x, qw, kw, vw, ow (fp32)
// ---------------------------------------------------------------------------
extern "C" void kernel_launch(void* const* d_in, const int* in_sizes, int n_in,
                              void* d_out, int out_size) {
    const float* x = (const float*)d_in[0];
    float* out = (float*)d_out;

    __nv_bfloat16 *xh, *xl, *ah, *al, *wh, *wl;
    cudaGetSymbolAddress((void**)&xh, g_xh);
    cudaGetSymbolAddress((void**)&xl, g_xl);
    cudaGetSymbolAddress((void**)&ah, g_ah);
    cudaGetSymbolAddress((void**)&al, g_al);
    cudaGetSymbolAddress((void**)&wh, g_wh);
    cudaGetSymbolAddress((void**)&wl, g_wl);

    cudaFuncSetAttribute(gemm_pipe<1>, cudaFuncAttributeMaxDynamicSharedMemorySize,
                         GEMM_SMEM);
    cudaFuncSetAttribute(gemm_pipe<0>, cudaFuncAttributeMaxDynamicSharedMemorySize,
                         GEMM_SMEM);
    cudaFuncSetAttribute(attn_tc, cudaFuncAttributeMaxDynamicSharedMemorySize,
                         ATTN_SMEM);

    // 1. split x into bf16 hi/lo
    split_fp32<<<(ROWS * D_MODEL / 4) / 256, 256>>>(x, xh, xl);
    // 2. transpose+split all 4 weights (one launch)
    transpose_split4<<<dim3(32, 32, 4), dim3(32, 8)>>>(
        (const float*)d_in[1], (const float*)d_in[2],
        (const float*)d_in[3], (const float*)d_in[4]);

    // 3. fused Q/K/V projections (pipelined, one launch)
    gemm_pipe<1><<<dim3(D_MODEL / 128, ROWS / 128, 3), 256, GEMM_SMEM>>>(
        nullptr, nullptr, nullptr, nullptr, nullptr, nullptr, nullptr);

    // 4. tensor-core attention (BLOCK_M=128, writes ah/al)
    attn_tc<<<dim3(SEQ / 128, BATCH * N_HEADS), 256, ATTN_SMEM>>>();

    // 5. output projection (fp32 epilogue to d_out)
    gemm_pipe<0><<<dim3(D_MODEL / 128, ROWS / 128, 1), 256, GEMM_SMEM>>>(
        ah, al, wh + 3u * D_MODEL * D_MODEL, wl + 3u * D_MODEL * D_MODEL,
        out, nullptr, nullptr);
}

// round 10
// speedup vs baseline: 1.7239x; 1.7239x over previous
#include <cuda_runtime.h>
#include <cuda_bf16.h>
#include <cstdint>
#include <cstddef>

#define D_MODEL 1024
#define N_HEADS 16
#define HEAD_DIM 64
#define BATCH 2
#define SEQ 2048
#define ROWS (BATCH * SEQ)   // 4096

// ---------------- scratch (__device__ globals; allocation-free rule) -------
__device__ __nv_bfloat16 g_xh[ROWS * D_MODEL];
__device__ __nv_bfloat16 g_xl[ROWS * D_MODEL];
__device__ __nv_bfloat16 g_qh[ROWS * D_MODEL];
__device__ __nv_bfloat16 g_ql[ROWS * D_MODEL];
__device__ __nv_bfloat16 g_kh[ROWS * D_MODEL];
__device__ __nv_bfloat16 g_kl[ROWS * D_MODEL];
__device__ __nv_bfloat16 g_vh[ROWS * D_MODEL];
__device__ __nv_bfloat16 g_vl[ROWS * D_MODEL];
__device__ __nv_bfloat16 g_ah[ROWS * D_MODEL];
__device__ __nv_bfloat16 g_al[ROWS * D_MODEL];
__device__ __nv_bfloat16 g_wh[4 * D_MODEL * D_MODEL];  // transposed [N,K]
__device__ __nv_bfloat16 g_wl[4 * D_MODEL * D_MODEL];

// ---------------- helpers --------------------------------------------------
__device__ __forceinline__ uint32_t smem_u32(const void* p) {
    uint32_t a;
    asm("{ .reg .u64 t; cvta.to.shared.u64 t, %1; cvt.u32.u64 %0, t; }"
        : "=r"(a) : "l"(p));
    return a;
}

__device__ __forceinline__ void cp16(uint32_t s, const void* g) {
    asm volatile("cp.async.cg.shared.global [%0], [%1], 16;" :: "r"(s), "l"(g));
}
#define CP_COMMIT() asm volatile("cp.async.commit_group;" ::: "memory")
#define CP_WAIT(n)  asm volatile("cp.async.wait_group %0;" :: "n"(n) : "memory")

__device__ __forceinline__ void ldsm_x4(uint32_t addr, uint32_t& r0, uint32_t& r1,
                                        uint32_t& r2, uint32_t& r3) {
    asm volatile("ldmatrix.sync.aligned.m8n8.x4.shared.b16 {%0,%1,%2,%3}, [%4];"
                 : "=r"(r0), "=r"(r1), "=r"(r2), "=r"(r3) : "r"(addr));
}

__device__ __forceinline__ void ldsm_x4_t(uint32_t addr, uint32_t& r0, uint32_t& r1,
                                          uint32_t& r2, uint32_t& r3) {
    asm volatile("ldmatrix.sync.aligned.m8n8.x4.trans.shared.b16 {%0,%1,%2,%3}, [%4];"
                 : "=r"(r0), "=r"(r1), "=r"(r2), "=r"(r3) : "r"(addr));
}

__device__ __forceinline__ void mma16816(float* c, const uint32_t* a, const uint32_t* b) {
    asm volatile(
        "mma.sync.aligned.m16n8k16.row.col.f32.bf16.bf16.f32 "
        "{%0,%1,%2,%3},{%4,%5,%6,%7},{%8,%9},{%0,%1,%2,%3};"
        : "+f"(c[0]), "+f"(c[1]), "+f"(c[2]), "+f"(c[3])
        : "r"(a[0]), "r"(a[1]), "r"(a[2]), "r"(a[3]), "r"(b[0]), "r"(b[1]));
}

__device__ __forceinline__ uint32_t pack_bf16(float lo, float hi) {
    uint32_t r;
    asm("cvt.rn.bf16x2.f32 %0, %1, %2;" : "=r"(r) : "f"(hi), "f"(lo));
    return r;
}

__device__ __forceinline__ float bf16_rt(float v) {
    return __bfloat162float(__float2bfloat16(v));
}

// ---------------------------------------------------------------------------
// Pipelined split-bf16 GEMM (cp.async double-buffer), 2 CTAs/SM forced.
// C[M,N] = (Ah+Al)[M,K] @ (Bh+Bl)^T, B transposed [N,K]. CTA tile 128x128,
// BK=32, 256 threads, warp tile m32 x n64. Product AhBh + AlBh + AhBl.
// ---------------------------------------------------------------------------
#define GK 1024
#define NCH (GK / 32)                // 32
#define TS 40
#define TILE_HALVES (128 * TS)       // 5120
#define TILE_BYTES (TILE_HALVES * 2) // 10240
#define STAGE_BYTES (4 * TILE_BYTES) // 40960
#define GEMM_SMEM (2 * STAGE_BYTES)  // 81920

template <int QKV>
__global__ __launch_bounds__(256, 2) void gemm_pipe(
    const __nv_bfloat16* __restrict__ Ah, const __nv_bfloat16* __restrict__ Al,
    const __nv_bfloat16* __restrict__ Bh, const __nv_bfloat16* __restrict__ Bl,
    float* __restrict__ C, __nv_bfloat16* __restrict__ H,
    __nv_bfloat16* __restrict__ L) {
    extern __shared__ __align__(16) char gsm[];
    if (QKV) {
        const size_t zo = (size_t)blockIdx.z * D_MODEL * D_MODEL;
        Ah = g_xh; Al = g_xl;
        Bh = g_wh + zo; Bl = g_wl + zo;
        H = blockIdx.z == 0 ? g_qh : blockIdx.z == 1 ? g_kh : g_vh;
        L = blockIdx.z == 0 ? g_ql : blockIdx.z == 1 ? g_kl : g_vl;
    }

    const int tid = threadIdx.x;
    const int lane = tid & 31;
    const int wid = tid >> 5;
    const int wm = wid & 3;
    const int wn = wid >> 2;
    const int mBase = wm * 32;
    const int nBase = wn * 64;
    const int bm = blockIdx.y * 128;
    const int bn = blockIdx.x * 128;
    const uint32_t sb = smem_u32(gsm);

    const int ld_r = tid >> 2, ld_c = (tid & 3) * 8;

    float c[2][8][4];
#pragma unroll
    for (int mt = 0; mt < 2; mt++)
#pragma unroll
        for (int nt = 0; nt < 8; nt++)
#pragma unroll
            for (int j = 0; j < 4; j++) c[mt][nt][j] = 0.0f;

    const int a_row = lane & 15;
    const int a_koff = (lane >> 4) * 8;
    const int b_nrow = ((lane >> 4) * 8) + (lane & 7);
    const int b_koff = ((lane >> 3) & 1) * 8;

    auto issue = [&](int ch, int stage) {
        const int k0 = ch * 32;
        const __nv_bfloat16* srcs[4] = {
            Ah + (size_t)bm * GK + k0, Al + (size_t)bm * GK + k0,
            Bh + (size_t)bn * GK + k0, Bl + (size_t)bn * GK + k0};
        const uint32_t sbase = sb + stage * STAGE_BYTES;
#pragma unroll
        for (int t = 0; t < 4; t++) {
#pragma unroll
            for (int it = 0; it < 2; it++) {
                int r = ld_r + it * 64;
                cp16(sbase + t * TILE_BYTES + (r * TS + ld_c) * 2,
                     srcs[t] + (size_t)r * GK + ld_c);
            }
        }
        CP_COMMIT();
    };

    issue(0, 0);

    for (int ch = 0; ch < NCH; ch++) {
        if (ch + 1 < NCH) {
            issue(ch + 1, (ch + 1) & 1);
            CP_WAIT(1);
        } else {
            CP_WAIT(0);
        }
        __syncthreads();
        const uint32_t base = sb + (ch & 1) * STAGE_BYTES;

#pragma unroll
        for (int ks = 0; ks < 2; ks++) {
            uint32_t aH[2][4], aL[2][4], b[8][2];
#pragma unroll
            for (int mt = 0; mt < 2; mt++) {
                uint32_t off = ((mBase + mt * 16 + a_row) * TS + ks * 16 + a_koff) * 2;
                ldsm_x4(base + off, aH[mt][0], aH[mt][1], aH[mt][2], aH[mt][3]);
                ldsm_x4(base + TILE_BYTES + off, aL[mt][0], aL[mt][1], aL[mt][2], aL[mt][3]);
            }
#pragma unroll
            for (int g = 0; g < 4; g++) {
                uint32_t off = ((nBase + g * 16 + b_nrow) * TS + ks * 16 + b_koff) * 2;
                ldsm_x4(base + 2 * TILE_BYTES + off,
                        b[2 * g][0], b[2 * g][1], b[2 * g + 1][0], b[2 * g + 1][1]);
            }
#pragma unroll
            for (int mt = 0; mt < 2; mt++)
#pragma unroll
                for (int nt = 0; nt < 8; nt++) mma16816(c[mt][nt], aH[mt], b[nt]);
#pragma unroll
            for (int mt = 0; mt < 2; mt++)
#pragma unroll
                for (int nt = 0; nt < 8; nt++) mma16816(c[mt][nt], aL[mt], b[nt]);
#pragma unroll
            for (int g = 0; g < 4; g++) {
                uint32_t off = ((nBase + g * 16 + b_nrow) * TS + ks * 16 + b_koff) * 2;
                ldsm_x4(base + 3 * TILE_BYTES + off,
                        b[2 * g][0], b[2 * g][1], b[2 * g + 1][0], b[2 * g + 1][1]);
            }
#pragma unroll
            for (int mt = 0; mt < 2; mt++)
#pragma unroll
                for (int nt = 0; nt < 8; nt++) mma16816(c[mt][nt], aH[mt], b[nt]);
        }
        __syncthreads();
    }

#pragma unroll
    for (int mt = 0; mt < 2; mt++) {
#pragma unroll
        for (int half = 0; half < 2; half++) {
            int row = bm + mBase + mt * 16 + (lane >> 2) + half * 8;
#pragma unroll
            for (int nt = 0; nt < 8; nt++) {
                int col = bn + nBase + nt * 8 + (lane & 3) * 2;
                float v0 = c[mt][nt][2 * half];
                float v1 = c[mt][nt][2 * half + 1];
                if (QKV) {
                    size_t off = (size_t)row * D_MODEL + col;
                    float h0 = bf16_rt(v0), h1 = bf16_rt(v1);
                    *(uint32_t*)(H + off) = pack_bf16(h0, h1);
                    *(uint32_t*)(L + off) = pack_bf16(v0 - h0, v1 - h1);
                } else {
                    *(float2*)(C + (size_t)row * D_MODEL + col) = make_float2(v0, v1);
                }
            }
        }
    }
}

// ---------------------------------------------------------------------------
// Conversion kernels
// ---------------------------------------------------------------------------
__global__ __launch_bounds__(256) void split_fp32(const float* __restrict__ s,
                                                  __nv_bfloat16* __restrict__ h,
                                                  __nv_bfloat16* __restrict__ l) {
    int i = blockIdx.x * 256 + threadIdx.x;
    float4 v = ((const float4*)s)[i];
    float a[4] = {v.x, v.y, v.z, v.w};
    uint32_t hh[2], ll[2];
#pragma unroll
    for (int j = 0; j < 2; j++) {
        float h0 = bf16_rt(a[2 * j]), h1 = bf16_rt(a[2 * j + 1]);
        hh[j] = pack_bf16(h0, h1);
        ll[j] = pack_bf16(a[2 * j] - h0, a[2 * j + 1] - h1);
    }
    ((uint32_t*)h)[2 * i] = hh[0];
    ((uint32_t*)h)[2 * i + 1] = hh[1];
    ((uint32_t*)l)[2 * i] = ll[0];
    ((uint32_t*)l)[2 * i + 1] = ll[1];
}

__global__ __launch_bounds__(256) void transpose_split4(const float* __restrict__ w0,
                                                        const float* __restrict__ w1,
                                                        const float* __restrict__ w2,
                                                        const float* __restrict__ w3) {
    __shared__ float t[32][33];
    const int z = blockIdx.z;
    const float* W = z == 0 ? w0 : z == 1 ? w1 : z == 2 ? w2 : w3;
    __nv_bfloat16* Th = g_wh + (size_t)z * D_MODEL * D_MODEL;
    __nv_bfloat16* Tl = g_wl + (size_t)z * D_MODEL * D_MODEL;

    int x = blockIdx.x * 32 + threadIdx.x;
    int y0 = blockIdx.y * 32;
#pragma unroll
    for (int j = 0; j < 32; j += 8)
        t[threadIdx.y + j][threadIdx.x] = W[(size_t)(y0 + threadIdx.y + j) * D_MODEL + x];
    __syncthreads();
    int xo = blockIdx.y * 32 + threadIdx.x;
    int yo = blockIdx.x * 32;
#pragma unroll
    for (int j = 0; j < 32; j += 8) {
        float v = t[threadIdx.x][threadIdx.y + j];
        float hv = bf16_rt(v);
        Th[(size_t)(yo + threadIdx.y + j) * D_MODEL + xo] = __float2bfloat16(v);
        Tl[(size_t)(yo + threadIdx.y + j) * D_MODEL + xo] = __float2bfloat16(v - hv);
    }
}

// ---------------------------------------------------------------------------
// Tensor-core causal flash attention — EXACT R6 version (181us verified).
// 64x64 tiles, 128 threads, 2-stage cp.async KV prefetch, split-bf16.
// ---------------------------------------------------------------------------
#define TS2 72
#define ATILE_B (64 * TS2 * 2)       // 9216 bytes per tile
#define KV_STAGE (4 * ATILE_B)       // 36864
#define ATTN_SMEM (2 * ATILE_B + 2 * KV_STAGE)  // 92160

__global__ __launch_bounds__(128, 1) void attn_tc() {
    extern __shared__ __align__(16) char asmc[];
    const uint32_t sb = smem_u32(asmc);

    const int tid = threadIdx.x;
    const int lane = tid & 31;
    const int wq = tid >> 5;
    const int qb = gridDim.x - 1 - blockIdx.x;  // heavy blocks first
    const int bh = blockIdx.y;
    const int b = bh >> 4, h = bh & 15;

    // ---- Q loads ----
    {
        const size_t base = (size_t)(b * SEQ + qb * 64) * D_MODEL + h * 64;
#pragma unroll
        for (int it = 0; it < 4; it++) {
            int idx = tid + it * 128;
            int r = idx >> 3, c8 = (idx & 7) * 8;
            size_t g = base + (size_t)r * D_MODEL + c8;
            uint32_t so = (r * TS2 + c8) * 2;
            cp16(sb + so, g_qh + g);
            cp16(sb + ATILE_B + so, g_ql + g);
        }
        CP_COMMIT();
    }

    auto issue_kv = [&](int kb, int stage) {
        const size_t base = (size_t)(b * SEQ + kb * 64) * D_MODEL + h * 64;
        const uint32_t kvb = sb + 2 * ATILE_B + stage * KV_STAGE;
#pragma unroll
        for (int it = 0; it < 4; it++) {
            int idx = tid + it * 128;
            int r = idx >> 3, c8 = (idx & 7) * 8;
            size_t g = base + (size_t)r * D_MODEL + c8;
            uint32_t so = (r * TS2 + c8) * 2;
            cp16(kvb + so, g_kh + g);
            cp16(kvb + ATILE_B + so, g_kl + g);
            cp16(kvb + 2 * ATILE_B + so, g_vh + g);
            cp16(kvb + 3 * ATILE_B + so, g_vl + g);
        }
        CP_COMMIT();
    };

    issue_kv(0, 0);

    float O[8][4];
#pragma unroll
    for (int nt = 0; nt < 8; nt++)
#pragma unroll
        for (int j = 0; j < 4; j++) O[nt][j] = 0.0f;
    float mrow[2] = {-1e30f, -1e30f};
    float lrow[2] = {0.0f, 0.0f};

    const float scale = 0.03125f;

    const uint32_t a_off = ((wq * 16 + (lane & 15)) * TS2 + (lane >> 4) * 8) * 2;
    const uint32_t b_off = ((((lane >> 4) * 8) + (lane & 7)) * TS2 + ((lane >> 3) & 1) * 8) * 2;
    const uint32_t v_off = ((((lane >> 3) & 1) * 8 + (lane & 7)) * TS2 + (lane >> 4) * 8) * 2;

    const int row0 = qb * 64 + wq * 16 + (lane >> 2);

    for (int kb = 0; kb <= qb; kb++) {
        if (kb < qb) {
            issue_kv(kb + 1, (kb + 1) & 1);
            CP_WAIT(1);
        } else {
            CP_WAIT(0);
        }
        __syncthreads();

        const uint32_t kvb = sb + 2 * ATILE_B + (kb & 1) * KV_STAGE;
        const uint32_t SKH = kvb, SKL = kvb + ATILE_B,
                       SVH = kvb + 2 * ATILE_B, SVL = kvb + 3 * ATILE_B;

        // ---- S = Q @ K^T (split) ----
        float s[8][4];
#pragma unroll
        for (int nt = 0; nt < 8; nt++)
#pragma unroll
            for (int j = 0; j < 4; j++) s[nt][j] = 0.0f;

#pragma unroll
        for (int ks = 0; ks < 4; ks++) {
            uint32_t aH[4], aL[4], bk[8][2];
            ldsm_x4(sb + a_off + ks * 32, aH[0], aH[1], aH[2], aH[3]);
            ldsm_x4(sb + ATILE_B + a_off + ks * 32, aL[0], aL[1], aL[2], aL[3]);
#pragma unroll
            for (int g = 0; g < 4; g++)
                ldsm_x4(SKH + b_off + g * 16 * TS2 * 2 + ks * 32,
                        bk[2 * g][0], bk[2 * g][1], bk[2 * g + 1][0], bk[2 * g + 1][1]);
#pragma unroll
            for (int nt = 0; nt < 8; nt++) mma16816(s[nt], aH, bk[nt]);
#pragma unroll
            for (int nt = 0; nt < 8; nt++) mma16816(s[nt], aL, bk[nt]);
#pragma unroll
            for (int g = 0; g < 4; g++)
                ldsm_x4(SKL + b_off + g * 16 * TS2 * 2 + ks * 32,
                        bk[2 * g][0], bk[2 * g][1], bk[2 * g + 1][0], bk[2 * g + 1][1]);
#pragma unroll
            for (int nt = 0; nt < 8; nt++) mma16816(s[nt], aH, bk[nt]);
        }

        // ---- scale + mask + online softmax ----
        const bool diag = (kb == qb);
#pragma unroll
        for (int i = 0; i < 2; i++) {
            const int rg = row0 + i * 8;
            float mx = -1e30f;
#pragma unroll
            for (int nt = 0; nt < 8; nt++) {
#pragma unroll
                for (int j = 0; j < 2; j++) {
                    int cg = kb * 64 + nt * 8 + (lane & 3) * 2 + j;
                    float v = s[nt][2 * i + j] * scale;
                    if (diag && cg > rg) v = -1e30f;
                    s[nt][2 * i + j] = v;
                    mx = fmaxf(mx, v);
                }
            }
            mx = fmaxf(mx, __shfl_xor_sync(0xffffffffu, mx, 1));
            mx = fmaxf(mx, __shfl_xor_sync(0xffffffffu, mx, 2));
            float mn = fmaxf(mrow[i], mx);
            float alpha = __expf(mrow[i] - mn);
            mrow[i] = mn;
            float rs = 0.0f;
#pragma unroll
            for (int nt = 0; nt < 8; nt++) {
#pragma unroll
                for (int j = 0; j < 2; j++) {
                    float p = __expf(s[nt][2 * i + j] - mn);
                    s[nt][2 * i + j] = p;
                    rs += p;
                }
            }
            rs += __shfl_xor_sync(0xffffffffu, rs, 1);
            rs += __shfl_xor_sync(0xffffffffu, rs, 2);
            lrow[i] = lrow[i] * alpha + rs;
#pragma unroll
            for (int nt = 0; nt < 8; nt++) {
                O[nt][2 * i] *= alpha;
                O[nt][2 * i + 1] *= alpha;
            }
        }

        // ---- O += P @ V (split) ----
#pragma unroll
        for (int g = 0; g < 4; g++) {
            uint32_t pH[4], pL[4];
#pragma unroll
            for (int q2 = 0; q2 < 2; q2++) {
#pragma unroll
                for (int half = 0; half < 2; half++) {
                    float v0 = s[2 * g + q2][2 * half];
                    float v1 = s[2 * g + q2][2 * half + 1];
                    float h0 = bf16_rt(v0), h1 = bf16_rt(v1);
                    pH[2 * q2 + half] = pack_bf16(h0, h1);
                    pL[2 * q2 + half] = pack_bf16(v0 - h0, v1 - h1);
                }
            }
            uint32_t bv[8][2];
#pragma unroll
            for (int gn = 0; gn < 4; gn++)
                ldsm_x4_t(SVH + v_off + (g * 16 * TS2 + gn * 16) * 2,
                          bv[2 * gn][0], bv[2 * gn][1], bv[2 * gn + 1][0], bv[2 * gn + 1][1]);
#pragma unroll
            for (int nt = 0; nt < 8; nt++) mma16816(O[nt], pH, bv[nt]);
#pragma unroll
            for (int nt = 0; nt < 8; nt++) mma16816(O[nt], pL, bv[nt]);
#pragma unroll
            for (int gn = 0; gn < 4; gn++)
                ldsm_x4_t(SVL + v_off + (g * 16 * TS2 + gn * 16) * 2,
                          bv[2 * gn][0], bv[2 * gn][1], bv[2 * gn + 1][0], bv[2 * gn + 1][1]);
#pragma unroll
            for (int nt = 0; nt < 8; nt++) mma16816(O[nt], pH, bv[nt]);
        }
        __syncthreads();
    }

    // ---- epilogue ----
#pragma unroll
    for (int i = 0; i < 2; i++) {
        float inv = 1.0f / lrow[i];
        size_t row = (size_t)(b * SEQ) + row0 + i * 8;
#pragma unroll
        for (int nt = 0; nt < 8; nt++) {
            size_t off = row * D_MODEL + h * 64 + nt * 8 + (lane & 3) * 2;
            float v0 = O[nt][2 * i] * inv;
            float v1 = O[nt][2 * i + 1] * inv;
            float h0 = bf16_rt(v0), h1 = bf16_rt(v1);
            *(uint32_t*)(g_ah + off) = pack_bf16(h0, h1);
            *(uint32_t*)(g_al + off) = pack_bf16(v0 - h0, v1 - h1);
        }
    }
}

// ---------------------------------------------------------------------------
// kernel_launch: x, qw, kw, vw, ow (fp32)
// ---------------------------------------------------------------------------
extern "C" void kernel_launch(void* const* d_in, const int* in_sizes, int n_in,
                              void* d_out, int out_size) {
    const float* x = (const float*)d_in[0];
    float* out = (float*)d_out;

    __nv_bfloat16 *xh, *xl, *ah, *al, *wh, *wl;
    cudaGetSymbolAddress((void**)&xh, g_xh);
    cudaGetSymbolAddress((void**)&xl, g_xl);
    cudaGetSymbolAddress((void**)&ah, g_ah);
    cudaGetSymbolAddress((void**)&al, g_al);
    cudaGetSymbolAddress((void**)&wh, g_wh);
    cudaGetSymbolAddress((void**)&wl, g_wl);

    cudaFuncSetAttribute(gemm_pipe<1>, cudaFuncAttributeMaxDynamicSharedMemorySize,
                         GEMM_SMEM);
    cudaFuncSetAttribute(gemm_pipe<0>, cudaFuncAttributeMaxDynamicSharedMemorySize,
                         GEMM_SMEM);
    cudaFuncSetAttribute(attn_tc, cudaFuncAttributeMaxDynamicSharedMemorySize,
                         ATTN_SMEM);

    // 1. split x into bf16 hi/lo
    split_fp32<<<(ROWS * D_MODEL / 4) / 256, 256>>>(x, xh, xl);
    // 2. transpose+split all 4 weights (one launch)
    transpose_split4<<<dim3(32, 32, 4), dim3(32, 8)>>>(
        (const float*)d_in[1], (const float*)d_in[2],
        (const float*)d_in[3], (const float*)d_in[4]);

    // 3. fused Q/K/V projections (pipelined, 2 CTAs/SM)
    gemm_pipe<1><<<dim3(D_MODEL / 128, ROWS / 128, 3), 256, GEMM_SMEM>>>(
        nullptr, nullptr, nullptr, nullptr, nullptr, nullptr, nullptr);

    // 4. tensor-core attention (R6 version)
    attn_tc<<<dim3(SEQ / 64, BATCH * N_HEADS), 128, ATTN_SMEM>>>();

    // 5. output projection (fp32 epilogue to d_out)
    gemm_pipe<0><<<dim3(D_MODEL / 128, ROWS / 128, 1), 256, GEMM_SMEM>>>(
        ah, al, wh + 3u * D_MODEL * D_MODEL, wl + 3u * D_MODEL * D_MODEL,
        out, nullptr, nullptr);
}